// round 1
// baseline (speedup 1.0000x reference)
#include <cuda_runtime.h>

#define D 96
#define MAXN 100000
#define MAXE 800000

// ---------------- device scratch (no allocation allowed) ----------------
__device__ int   g_src[MAXE];
__device__ int   g_dst[MAXE];
__device__ int   g_deg[MAXN];
__device__ int   g_off[MAXN + 1];
__device__ int   g_cursor[MAXN];
__device__ int   g_rank[MAXE];      // edge i -> its slot in CSR order
__device__ int   g_dsts[MAXE];      // dst sorted into CSR order
__device__ float g_es[MAXE];        // e weights in CSR order
__device__ float g_hg[MAXN * D];    // GEMM output (both layers)
__device__ float g_ha[MAXN * D];    // layer-1 aggregation output
__device__ float g_p[MAXN];
__device__ float g_q[MAXN];

// ---------------- edge_index normalization (int64 or int32) -------------
__global__ void k_convert(const void* __restrict__ ei, int E) {
    int i = blockIdx.x * blockDim.x + threadIdx.x;
    const int* p32 = (const int*)ei;
    // first N src entries are arange(N): int64 layout => 32-bit word 3 == 0
    bool is64 = (p32[3] == 0);
    if (i < E) {
        if (is64) {
            const long long* p64 = (const long long*)ei;
            g_src[i] = (int)p64[i];
            g_dst[i] = (int)p64[E + i];
        } else {
            g_src[i] = p32[i];
            g_dst[i] = p32[E + i];
        }
    }
}

__global__ void k_zero_deg(int n) {
    int i = blockIdx.x * blockDim.x + threadIdx.x;
    if (i < n) g_deg[i] = 0;
}

__global__ void k_count(int E) {
    int i = blockIdx.x * blockDim.x + threadIdx.x;
    if (i < E) atomicAdd(&g_deg[g_src[i]], 1);
}

// single-block exclusive scan over g_deg -> g_off, g_cursor
__global__ void k_scan(int n) {
    __shared__ int wsum[32];
    __shared__ int s_carry;
    int tid = threadIdx.x, lane = tid & 31, wid = tid >> 5;
    if (tid == 0) s_carry = 0;
    __syncthreads();
    for (int base = 0; base < n; base += 1024) {
        int i = base + tid;
        int v = (i < n) ? g_deg[i] : 0;
        int x = v;
        #pragma unroll
        for (int o = 1; o < 32; o <<= 1) {
            int t = __shfl_up_sync(0xffffffffu, x, o);
            if (lane >= o) x += t;
        }
        if (lane == 31) wsum[wid] = x;
        __syncthreads();
        if (wid == 0) {
            int y = wsum[lane];
            #pragma unroll
            for (int o = 1; o < 32; o <<= 1) {
                int t = __shfl_up_sync(0xffffffffu, y, o);
                if (lane >= o) y += t;
            }
            wsum[lane] = y;
        }
        __syncthreads();
        int carry = s_carry;
        int warpoff = (wid > 0) ? wsum[wid - 1] : 0;
        int excl = x + warpoff - v;
        if (i < n) {
            g_off[i] = carry + excl;
            g_cursor[i] = carry + excl;
        }
        __syncthreads();
        if (tid == 1023) s_carry = carry + wsum[31];
        __syncthreads();
    }
    if (threadIdx.x == 0) g_off[n] = s_carry;
}

__global__ void k_scatter(int E) {
    int i = blockIdx.x * blockDim.x + threadIdx.x;
    if (i < E) {
        int s = g_src[i];
        int pos = atomicAdd(&g_cursor[s], 1);
        g_rank[i] = pos;
        g_dsts[pos] = g_dst[i];
    }
}

// ---------------- GEMM: C[n,96] = A[n,96] @ W[96,96] --------------------
// tile M=128, full N=96, K chunked by 32. 256 threads = 16x16, each thread
// computes an 8x6 microtile.
__global__ __launch_bounds__(256) void k_gemm(const float* __restrict__ Aext,
                                              int useExt,
                                              const float* __restrict__ W,
                                              int n) {
    __shared__ float Xs[128 * 33];
    __shared__ float Ws[32 * 96];
    const float* A = useExt ? Aext : g_ha;

    int tx = threadIdx.x & 15;
    int ty = threadIdx.x >> 4;
    int rowBase = blockIdx.x * 128;

    float acc[8][6];
    #pragma unroll
    for (int r = 0; r < 8; r++)
        #pragma unroll
        for (int c = 0; c < 6; c++) acc[r][c] = 0.f;

    for (int kc = 0; kc < 3; kc++) {
        for (int idx = threadIdx.x; idx < 128 * 32; idx += 256) {
            int r = idx >> 5, c = idx & 31;
            int gr = rowBase + r;
            Xs[r * 33 + c] = (gr < n) ? A[gr * 96 + kc * 32 + c] : 0.f;
        }
        for (int idx = threadIdx.x; idx < 32 * 96; idx += 256) {
            int r = idx / 96, c = idx - r * 96;
            Ws[idx] = W[(kc * 32 + r) * 96 + c];
        }
        __syncthreads();
        #pragma unroll 8
        for (int k = 0; k < 32; k++) {
            float xv[8], wv[6];
            #pragma unroll
            for (int r = 0; r < 8; r++) xv[r] = Xs[(ty * 8 + r) * 33 + k];
            #pragma unroll
            for (int c = 0; c < 6; c++) wv[c] = Ws[k * 96 + tx * 6 + c];
            #pragma unroll
            for (int r = 0; r < 8; r++)
                #pragma unroll
                for (int c = 0; c < 6; c++) acc[r][c] += xv[r] * wv[c];
        }
        __syncthreads();
    }

    #pragma unroll
    for (int r = 0; r < 8; r++) {
        int gr = rowBase + ty * 8 + r;
        if (gr < n) {
            #pragma unroll
            for (int c = 0; c < 6; c++)
                g_hg[gr * 96 + tx * 6 + c] = acc[r][c];
        }
    }
}

// ---------------- per-node attention partial dots ------------------------
// p[u] = h[u]·a[0:96], q[u] = h[u]·a[96:192]; warp per node
__global__ void k_pq(const float* __restrict__ a, int n) {
    int w = (blockIdx.x * blockDim.x + threadIdx.x) >> 5;
    int lane = threadIdx.x & 31;
    if (w >= n) return;
    const float* hr = g_hg + w * 96;
    float ps = 0.f, qs = 0.f;
    #pragma unroll
    for (int t = 0; t < 3; t++) {
        int f = lane + t * 32;
        float hv = hr[f];
        ps += hv * a[f];
        qs += hv * a[96 + f];
    }
    #pragma unroll
    for (int o = 16; o; o >>= 1) {
        ps += __shfl_down_sync(0xffffffffu, ps, o);
        qs += __shfl_down_sync(0xffffffffu, qs, o);
    }
    if (lane == 0) { g_p[w] = ps; g_q[w] = qs; }
}

// ---------------- per-edge weight, written in CSR order ------------------
__global__ void k_edge(int E) {
    int i = blockIdx.x * blockDim.x + threadIdx.x;
    if (i < E) {
        float s = g_p[g_src[i]] + g_q[g_dst[i]];
        float l = s > 0.f ? s : 0.01f * s;     // leaky_relu
        g_es[g_rank[i]] = expf(-l);
    }
}

// ---------------- warp-per-node aggregation (atomic-free) ----------------
__global__ void k_agg(float* __restrict__ outExt, int useExt, int relu, int n) {
    int w = (blockIdx.x * blockDim.x + threadIdx.x) >> 5;
    int lane = threadIdx.x & 31;
    if (w >= n) return;
    float* out = useExt ? outExt : g_ha;
    int s = g_off[w], e = g_off[w + 1];
    float a0 = 0.f, a1 = 0.f, a2 = 0.f, se = 0.f;
    for (int j = s; j < e; j++) {
        float wt = g_es[j];
        int v = g_dsts[j];
        const float* hr = g_hg + v * 96;
        a0 += wt * hr[lane];
        a1 += wt * hr[lane + 32];
        a2 += wt * hr[lane + 64];
        se += wt;
    }
    float inv = 1.0f / se;
    a0 *= inv; a1 *= inv; a2 *= inv;
    if (relu) {
        a0 = fmaxf(a0, 0.f);
        a1 = fmaxf(a1, 0.f);
        a2 = fmaxf(a2, 0.f);
    }
    out[w * 96 + lane]      = a0;
    out[w * 96 + lane + 32] = a1;
    out[w * 96 + lane + 64] = a2;
}

// ---------------- launch -------------------------------------------------
extern "C" void kernel_launch(void* const* d_in, const int* in_sizes, int n_in,
                              void* d_out, int out_size) {
    const void*  ei = d_in[0];
    const float* x  = (const float*)d_in[1];
    const float* W1 = (const float*)d_in[2];
    const float* a1 = (const float*)d_in[3];
    const float* W2 = (const float*)d_in[4];
    const float* a2 = (const float*)d_in[5];
    float* out = (float*)d_out;

    int E = in_sizes[0] / 2;
    int n = in_sizes[1] / D;

    int eb = (E + 255) / 256;
    int nb = (n + 255) / 256;
    int gemmb = (n + 127) / 128;
    int warpb = (n * 32 + 255) / 256;   // warp-per-node kernels, 8 warps/block

    // structure build (recomputed every launch: deterministic)
    k_convert<<<eb, 256>>>(ei, E);
    k_zero_deg<<<nb, 256>>>(n);
    k_count<<<eb, 256>>>(E);
    k_scan<<<1, 1024>>>(n);
    k_scatter<<<eb, 256>>>(E);

    // layer 1
    k_gemm<<<gemmb, 256>>>(x, 1, W1, n);
    k_pq<<<warpb, 256>>>(a1, n);
    k_edge<<<eb, 256>>>(E);
    k_agg<<<warpb, 256>>>(out, 0, 0, n);   // -> g_ha

    // layer 2
    k_gemm<<<gemmb, 256>>>(nullptr, 0, W2, n);   // g_ha @ W2 -> g_hg
    k_pq<<<warpb, 256>>>(a2, n);
    k_edge<<<eb, 256>>>(E);
    k_agg<<<warpb, 256>>>(out, 1, 1, n);   // -> d_out with ReLU
}